// round 2
// baseline (speedup 1.0000x reference)
#include <cuda_runtime.h>
#include <cstdint>
#include <cmath>

// Problem constants (fixed by the dataset)
#define BB   8
#define TT   4096
#define DD   256
#define MTOT (BB*TT)        // 32768 tokens
#define NSEG 64
#define SEGL (TT/NSEG)      // 64

// ---------------- scratch (device globals: no runtime allocation) ----------------
__device__ float g_z[(size_t)MTOT*DD];
__device__ float g_f[(size_t)MTOT*DD];
__device__ float g_o[(size_t)MTOT*DD];
__device__ float g_segA[BB*NSEG*DD];
__device__ float g_segB[BB*NSEG*DD];
__device__ float g_carry[BB*NSEG*DD];

// ---------------- helpers ----------------
__device__ __forceinline__ uint32_t f2tf32(float x) {
    uint32_t r;
    asm("cvt.rna.tf32.f32 %0, %1;" : "=r"(r) : "f"(x));
    return r;
}

__device__ __forceinline__ void mma_tf32(float c[4], const uint32_t a[4], const uint32_t b[2]) {
    asm("mma.sync.aligned.m16n8k8.row.col.f32.tf32.tf32.f32 "
        "{%0,%1,%2,%3}, {%4,%5,%6,%7}, {%8,%9}, {%0,%1,%2,%3};"
        : "+f"(c[0]), "+f"(c[1]), "+f"(c[2]), "+f"(c[3])
        : "r"(a[0]), "r"(a[1]), "r"(a[2]), "r"(a[3]),
          "r"(b[0]), "r"(b[1]));
}

// ---------------- gate GEMM: G = [x_{t-1}; x_t] @ Wcat, fused activation ----------------
// M = 32768, N = 768 (3 gates x 256), K = 512 (2 taps x 256)
// BM=128, BN=128, BK=32; 8 warps (2x4), warp tile 64x32; m16n8k8 tf32.
__global__ __launch_bounds__(256)
void gates_gemm(const float* __restrict__ x,
                const float* __restrict__ Wz, const float* __restrict__ Wf,
                const float* __restrict__ Wo,
                const float* __restrict__ bz, const float* __restrict__ bfv,
                const float* __restrict__ bo)
{
    __shared__ uint32_t As[128][36];   // [m][k], padded: fragment reads conflict-free
    __shared__ uint32_t Bs[32][132];   // [k][n], padded

    const int tid = threadIdx.x;
    const int m0  = blockIdx.x * 128;
    const int n0  = blockIdx.y * 128;
    const int gate = n0 >> 8;          // BN=128 block always inside one gate
    const int n0g  = n0 & 255;

    const float* W    = (gate == 0) ? Wz  : (gate == 1) ? Wf  : Wo;   // [2][256][256]
    const float* bias = (gate == 0) ? bz  : (gate == 1) ? bfv : bo;
    float* dst        = (gate == 0) ? g_z : (gate == 1) ? g_f : g_o;

    const int warp = tid >> 5, lane = tid & 31;
    const int gq = lane >> 2, q = lane & 3;     // groupID / thread-in-group
    const int wm0 = (warp & 1) * 64;
    const int wn0 = (warp >> 1) * 32;

    float acc[4][4][4];
    #pragma unroll
    for (int mt = 0; mt < 4; mt++)
        #pragma unroll
        for (int nt = 0; nt < 4; nt++)
            #pragma unroll
            for (int i = 0; i < 4; i++) acc[mt][nt][i] = 0.0f;

    float4 pa[4], pb[4];

    // ---- global-load helpers (register prefetch) ----
    auto loadA = [&](int kb) {
        const int tap = kb >> 3;
        const int d0  = (kb & 7) * 32;
        #pragma unroll
        for (int p = 0; p < 4; p++) {
            int idx4 = tid + p * 256;          // 1024 float4 = 128 rows x 32 floats
            int row  = idx4 >> 3;
            int col  = (idx4 & 7) * 4;
            int m    = m0 + row;
            if (tap == 0) {
                if ((m & (TT - 1)) == 0) pa[p] = make_float4(0.f, 0.f, 0.f, 0.f);
                else pa[p] = *(const float4*)(x + (size_t)(m - 1) * DD + d0 + col);
            } else {
                pa[p] = *(const float4*)(x + (size_t)m * DD + d0 + col);
            }
        }
    };
    auto loadB = [&](int kb) {
        const int tap = kb >> 3;
        const int d0  = (kb & 7) * 32;
        #pragma unroll
        for (int p = 0; p < 4; p++) {
            int idx4 = tid + p * 256;          // 1024 float4 = 32 rows x 128 floats
            int row  = idx4 >> 5;
            int col  = (idx4 & 31) * 4;
            pb[p] = *(const float4*)(W + (size_t)tap * 65536 + (size_t)(d0 + row) * 256 + n0g + col);
        }
    };
    auto storeA = [&]() {
        #pragma unroll
        for (int p = 0; p < 4; p++) {
            int idx4 = tid + p * 256;
            int row  = idx4 >> 3;
            int col  = (idx4 & 7) * 4;
            uint4 t;
            t.x = f2tf32(pa[p].x); t.y = f2tf32(pa[p].y);
            t.z = f2tf32(pa[p].z); t.w = f2tf32(pa[p].w);
            *(uint4*)&As[row][col] = t;
        }
    };
    auto storeB = [&]() {
        #pragma unroll
        for (int p = 0; p < 4; p++) {
            int idx4 = tid + p * 256;
            int row  = idx4 >> 5;
            int col  = (idx4 & 31) * 4;
            uint4 t;
            t.x = f2tf32(pb[p].x); t.y = f2tf32(pb[p].y);
            t.z = f2tf32(pb[p].z); t.w = f2tf32(pb[p].w);
            *(uint4*)&Bs[row][col] = t;
        }
    };

    loadA(0); loadB(0);
    storeA(); storeB();
    __syncthreads();

    for (int kb = 0; kb < 16; kb++) {
        if (kb + 1 < 16) { loadA(kb + 1); loadB(kb + 1); }

        #pragma unroll
        for (int ks = 0; ks < 4; ks++) {
            const int ko = ks * 8;
            uint32_t afrag[4][4], bfrag[4][2];
            #pragma unroll
            for (int mt = 0; mt < 4; mt++) {
                int mb = wm0 + mt * 16 + gq;
                afrag[mt][0] = As[mb    ][ko + q    ];
                afrag[mt][1] = As[mb + 8][ko + q    ];
                afrag[mt][2] = As[mb    ][ko + q + 4];
                afrag[mt][3] = As[mb + 8][ko + q + 4];
            }
            #pragma unroll
            for (int nt = 0; nt < 4; nt++) {
                int nb = wn0 + nt * 8 + gq;
                bfrag[nt][0] = Bs[ko + q    ][nb];
                bfrag[nt][1] = Bs[ko + q + 4][nb];
            }
            #pragma unroll
            for (int mt = 0; mt < 4; mt++)
                #pragma unroll
                for (int nt = 0; nt < 4; nt++)
                    mma_tf32(acc[mt][nt], afrag[mt], bfrag[nt]);
        }

        __syncthreads();
        if (kb + 1 < 16) {
            storeA(); storeB();
            __syncthreads();
        }
    }

    // ---- epilogue: bias + activation, write gate scratch ----
    #pragma unroll
    for (int mt = 0; mt < 4; mt++) {
        #pragma unroll
        for (int nt = 0; nt < 4; nt++) {
            #pragma unroll
            for (int i = 0; i < 4; i++) {
                int m  = wm0 + mt * 16 + gq + ((i >> 1) << 3);
                int n  = wn0 + nt * 8 + q * 2 + (i & 1);
                int gm = m0 + m;
                int gn = n0g + n;
                float v = acc[mt][nt][i] + bias[gn];
                if (gate == 0) v = tanhf(v);
                else           v = 1.0f / (1.0f + expf(-v));
                dst[(size_t)gm * DD + gn] = v;
            }
        }
    }
}

// ---------------- segmented scan over the linear recurrence ----------------
// c_t = f_t*c_{t-1} + (1-f_t)*z_t ; composition (A,B) <- (f*A, f*B + (1-f)z)

__global__ void seg_reduce() {
    int tid = blockIdx.x * 256 + threadIdx.x;   // 131072 threads: (b, s, d)
    int d = tid & 255;
    int s = (tid >> 8) & (NSEG - 1);
    int b = tid >> 14;
    size_t base = ((size_t)b * TT + (size_t)s * SEGL) * DD + d;
    float A = 1.0f, Bv = 0.0f;
    #pragma unroll 4
    for (int i = 0; i < SEGL; i++) {
        float f = g_f[base + (size_t)i * DD];
        float z = g_z[base + (size_t)i * DD];
        A  = f * A;
        Bv = f * Bv + (1.0f - f) * z;
    }
    int sidx = (b * NSEG + s) * DD + d;
    g_segA[sidx] = A;
    g_segB[sidx] = Bv;
}

__global__ void seg_carry() {
    int tid = blockIdx.x * 256 + threadIdx.x;   // 2048 threads: (b, d)
    int d = tid & 255;
    int b = tid >> 8;
    float c = 0.0f;
    for (int s = 0; s < NSEG; s++) {
        int idx = (b * NSEG + s) * DD + d;
        g_carry[idx] = c;
        c = g_segA[idx] * c + g_segB[idx];
    }
}

__global__ void seg_apply(float* __restrict__ out) {
    int tid = blockIdx.x * 256 + threadIdx.x;   // 131072 threads: (b, s, d)
    int d = tid & 255;
    int s = (tid >> 8) & (NSEG - 1);
    int b = tid >> 14;
    size_t base = ((size_t)b * TT + (size_t)s * SEGL) * DD + d;
    float c = g_carry[(b * NSEG + s) * DD + d];
    #pragma unroll 4
    for (int i = 0; i < SEGL; i++) {
        size_t idx = base + (size_t)i * DD;
        float f = g_f[idx];
        float z = g_z[idx];
        float o = g_o[idx];
        c = f * c + (1.0f - f) * z;
        out[idx] = o * c;
    }
}

// ---------------- launch ----------------
extern "C" void kernel_launch(void* const* d_in, const int* in_sizes, int n_in,
                              void* d_out, int out_size) {
    const float* x   = (const float*)d_in[0];
    const float* Wz  = (const float*)d_in[1];
    const float* Wf  = (const float*)d_in[2];
    const float* Wo  = (const float*)d_in[3];
    const float* bz  = (const float*)d_in[4];
    const float* bfv = (const float*)d_in[5];
    const float* bo  = (const float*)d_in[6];
    float* out = (float*)d_out;

    gates_gemm<<<dim3(MTOT / 128, 768 / 128), 256>>>(x, Wz, Wf, Wo, bz, bfv, bo);
    seg_reduce<<<(BB * NSEG * DD) / 256, 256>>>();
    seg_carry<<<(BB * DD) / 256, 256>>>();
    seg_apply<<<(BB * NSEG * DD) / 256, 256>>>(out);
}

// round 7
// speedup vs baseline: 1.6645x; 1.6645x over previous
#include <cuda_runtime.h>
#include <cstdint>
#include <cmath>

// Problem constants
#define BB   8
#define TT   4096
#define DD   256
#define MTOT (BB*TT)        // 32768
#define KTOT 512            // 2 taps x 256
#define NSEG 64
#define SEGL (TT/NSEG)      // 64

// GEMM tiling
#define BM 128
#define BN 128
#define BK 32               // 32 tf32 = 128B per row
#define NKB (KTOT/BK)       // 16
#define STAGES 3
#define A_BYTES (BM*128)            // 16384
#define B_BYTES (BN*128)            // 16384
#define STAGE_BYTES (A_BYTES+B_BYTES)
#define DYN_SMEM (STAGES*STAGE_BYTES)   // 98304

// ---------------- scratch (device globals) ----------------
__device__ float g_z[(size_t)MTOT*DD];
__device__ float g_f[(size_t)MTOT*DD];
__device__ float g_o[(size_t)MTOT*DD];
__device__ float g_xt[(size_t)MTOT*DD];       // x pre-rounded to tf32 (RNA)
__device__ float g_wt[3*DD*KTOT];             // Wt[g][n][k], k-major, tf32-rounded
__device__ float g_segA[BB*NSEG*DD];
__device__ float g_segB[BB*NSEG*DD];
__device__ float g_carry[BB*NSEG*DD];

// ---------------- helpers ----------------
__device__ __forceinline__ uint32_t smem_u32(const void* p) {
    uint32_t a;
    asm("{ .reg .u64 t; cvta.to.shared.u64 t, %1; cvt.u32.u64 %0, t; }" : "=r"(a) : "l"(p));
    return a;
}
__device__ __forceinline__ float tf32_rna(float x) {
    uint32_t r;
    asm("cvt.rna.tf32.f32 %0, %1;" : "=r"(r) : "f"(x));
    return __uint_as_float(r);
}
__device__ __forceinline__ void cp_async16(uint32_t dst, const void* src, uint32_t src_bytes) {
    asm volatile("cp.async.cg.shared.global [%0], [%1], 16, %2;"
                 :: "r"(dst), "l"(src), "r"(src_bytes) : "memory");
}
__device__ __forceinline__ void cp_commit() {
    asm volatile("cp.async.commit_group;" ::: "memory");
}
template<int N> __device__ __forceinline__ void cp_wait() {
    asm volatile("cp.async.wait_group %0;" :: "n"(N) : "memory");
}
__device__ __forceinline__ void ldsm4(uint32_t& r0, uint32_t& r1, uint32_t& r2, uint32_t& r3,
                                      uint32_t addr) {
    asm volatile("ldmatrix.sync.aligned.m8n8.x4.shared.b16 {%0,%1,%2,%3}, [%4];"
                 : "=r"(r0), "=r"(r1), "=r"(r2), "=r"(r3) : "r"(addr));
}
__device__ __forceinline__ void mma_tf32(float c[4], const uint32_t a[4], const uint32_t b[2]) {
    asm("mma.sync.aligned.m16n8k8.row.col.f32.tf32.tf32.f32 "
        "{%0,%1,%2,%3}, {%4,%5,%6,%7}, {%8,%9}, {%0,%1,%2,%3};"
        : "+f"(c[0]), "+f"(c[1]), "+f"(c[2]), "+f"(c[3])
        : "r"(a[0]), "r"(a[1]), "r"(a[2]), "r"(a[3]), "r"(b[0]), "r"(b[1]));
}

// ---------------- prep kernels ----------------
__global__ void cvt_x(const float* __restrict__ x) {
    size_t i = (size_t)blockIdx.x * 256 + threadIdx.x;   // over float4s
    float4 v = ((const float4*)x)[i];
    v.x = tf32_rna(v.x); v.y = tf32_rna(v.y); v.z = tf32_rna(v.z); v.w = tf32_rna(v.w);
    ((float4*)g_xt)[i] = v;
}

__global__ void trans_w(const float* __restrict__ Wz, const float* __restrict__ Wf,
                        const float* __restrict__ Wo) {
    __shared__ float t[32][33];
    int g = blockIdx.z, tap = blockIdx.y;
    const float* W = (g == 0) ? Wz : (g == 1) ? Wf : Wo;
    int d0 = (blockIdx.x & 7) * 32;
    int n0 = (blockIdx.x >> 3) * 32;
    #pragma unroll
    for (int r = 0; r < 4; r++) {
        int d = d0 + threadIdx.y + r * 8;
        t[threadIdx.y + r * 8][threadIdx.x] =
            tf32_rna(W[(size_t)tap * 65536 + (size_t)d * 256 + n0 + threadIdx.x]);
    }
    __syncthreads();
    #pragma unroll
    for (int r = 0; r < 4; r++) {
        int n = n0 + threadIdx.y + r * 8;
        g_wt[(size_t)g * (DD * KTOT) + (size_t)n * KTOT + tap * 256 + d0 + threadIdx.x] =
            t[threadIdx.x][threadIdx.y + r * 8];
    }
}

// ---------------- mma.sync tf32 gate GEMM ----------------
// BM=128, BN=128, BK=32, 3-stage cp.async pipeline, ldmatrix fragments.
// 8 warps (2 m x 4 n), warp tile 64x32, m16n8k8.
__global__ __launch_bounds__(256)
void gates_gemm(const float* __restrict__ bz, const float* __restrict__ bfv,
                const float* __restrict__ bo) {
    extern __shared__ char dyn[];
    const uint32_t sbase = smem_u32(dyn);

    const int tid  = threadIdx.x;
    const int warp = tid >> 5, lane = tid & 31;
    const int gq = lane >> 2, q = lane & 3;
    const int wm0 = (warp & 1) * 64;
    const int wn0 = (warp >> 1) * 32;

    const int n0   = blockIdx.x * BN;      // n fast -> A reuse in L2 within a wave
    const int m0   = blockIdx.y * BM;
    const int gate = n0 >> 8;
    const int n0g  = n0 & 255;

    const float* bias = (gate == 0) ? bz : (gate == 1) ? bfv : bo;
    float* dst        = (gate == 0) ? g_z : (gate == 1) ? g_f : g_o;
    const float* Wb   = g_wt + (size_t)gate * (DD * KTOT) + (size_t)n0g * KTOT;

    float acc[4][4][4];
    #pragma unroll
    for (int mt = 0; mt < 4; mt++)
        #pragma unroll
        for (int nt = 0; nt < 4; nt++)
            #pragma unroll
            for (int i = 0; i < 4; i++) acc[mt][nt][i] = 0.0f;

    // ---- cp.async producer: one BK stage (A 16KB + B 16KB) ----
    auto issue_stage = [&](int kb, int st) {
        const uint32_t abase = sbase + st * STAGE_BYTES;
        const uint32_t bbase = abase + A_BYTES;
        const int tap = kb >> 3;
        const int d0  = (kb & 7) << 5;
        #pragma unroll
        for (int p = 0; p < 4; p++) {
            int idx = tid + p * 256;       // 1024 chunks of 16B
            int row = idx >> 3;
            int k4  = idx & 7;
            uint32_t sw = (uint32_t)(row << 7) + (uint32_t)((k4 ^ (row & 7)) << 4);
            // A
            int m = m0 + row;
            const float* srcA;
            uint32_t nb = 16;
            if (tap == 0) {
                srcA = g_xt + (size_t)(m - 1) * DD + d0 + (k4 << 2);
                if ((m & (TT - 1)) == 0) { nb = 0; srcA = g_xt; }
            } else {
                srcA = g_xt + (size_t)m * DD + d0 + (k4 << 2);
            }
            cp_async16(abase + sw, srcA, nb);
            // B (n-major, k contiguous)
            const float* srcB = Wb + (size_t)row * KTOT + (kb << 5) + (k4 << 2);
            cp_async16(bbase + sw, srcB, 16);
        }
    };

    // ---- consumer: one BK stage of MMAs ----
    const int mi1 = (lane >> 3) & 1;    // matrix pair selector bits
    const int mi2 = lane >> 4;
    const int rr  = lane & 7;
    auto compute = [&](int st) {
        const uint32_t ab = sbase + st * STAGE_BYTES;
        const uint32_t bb = ab + A_BYTES;
        #pragma unroll
        for (int ks = 0; ks < 4; ks++) {
            uint32_t af[4][4], bf[4][2];
            #pragma unroll
            for (int mt = 0; mt < 4; mt++) {
                int row = wm0 + mt * 16 + mi1 * 8 + rr;
                int k4  = ks * 2 + mi2;
                uint32_t addr = ab + (row << 7) + ((k4 ^ (row & 7)) << 4);
                ldsm4(af[mt][0], af[mt][1], af[mt][2], af[mt][3], addr);
            }
            #pragma unroll
            for (int ntp = 0; ntp < 2; ntp++) {
                int row = wn0 + ntp * 16 + mi2 * 8 + rr;
                int k4  = ks * 2 + mi1;
                uint32_t addr = bb + (row << 7) + ((k4 ^ (row & 7)) << 4);
                uint32_t r0, r1, r2, r3;
                ldsm4(r0, r1, r2, r3, addr);
                bf[2*ntp][0] = r0; bf[2*ntp][1] = r1;
                bf[2*ntp+1][0] = r2; bf[2*ntp+1][1] = r3;
            }
            #pragma unroll
            for (int mt = 0; mt < 4; mt++)
                #pragma unroll
                for (int nt = 0; nt < 4; nt++)
                    mma_tf32(acc[mt][nt], af[mt], bf[nt]);
        }
    };

    // ---- pipeline ----
    issue_stage(0, 0); cp_commit();
    issue_stage(1, 1); cp_commit();

    int st = 0;
    for (int kb = 0; kb < NKB; kb++) {
        cp_wait<1>();
        __syncthreads();
        compute(st);
        if (kb + 2 < NKB) issue_stage(kb + 2, (kb + 2) % STAGES);   // FIX: proper mod-3
        cp_commit();
        st = (st + 1 == STAGES) ? 0 : st + 1;
    }

    // ---- epilogue: bias + activation, float2 stores ----
    #pragma unroll
    for (int mt = 0; mt < 4; mt++) {
        #pragma unroll
        for (int nt = 0; nt < 4; nt++) {
            #pragma unroll
            for (int h = 0; h < 2; h++) {       // i = 2h, 2h+1
                int m  = m0 + wm0 + mt * 16 + gq + h * 8;
                int n  = n0g + wn0 + nt * 8 + q * 2;
                float v0 = acc[mt][nt][2*h]   + bias[n];
                float v1 = acc[mt][nt][2*h+1] + bias[n + 1];
                if (gate == 0) { v0 = tanhf(v0); v1 = tanhf(v1); }
                else { v0 = 1.0f / (1.0f + expf(-v0)); v1 = 1.0f / (1.0f + expf(-v1)); }
                *(float2*)(dst + (size_t)m * DD + n) = make_float2(v0, v1);
            }
        }
    }
}

// ---------------- segmented scan (proven) ----------------
__global__ void seg_reduce() {
    int tid = blockIdx.x * 256 + threadIdx.x;
    int d = tid & 255;
    int s = (tid >> 8) & (NSEG - 1);
    int b = tid >> 14;
    size_t base = ((size_t)b * TT + (size_t)s * SEGL) * DD + d;
    float A = 1.0f, Bv = 0.0f;
    #pragma unroll 4
    for (int i = 0; i < SEGL; i++) {
        float f = g_f[base + (size_t)i * DD];
        float z = g_z[base + (size_t)i * DD];
        A  = f * A;
        Bv = f * Bv + (1.0f - f) * z;
    }
    int sidx = (b * NSEG + s) * DD + d;
    g_segA[sidx] = A;
    g_segB[sidx] = Bv;
}

__global__ void seg_carry() {
    int tid = blockIdx.x * 256 + threadIdx.x;
    int d = tid & 255;
    int b = tid >> 8;
    float c = 0.0f;
    for (int s = 0; s < NSEG; s++) {
        int idx = (b * NSEG + s) * DD + d;
        g_carry[idx] = c;
        c = g_segA[idx] * c + g_segB[idx];
    }
}

__global__ void seg_apply(float* __restrict__ out) {
    int tid = blockIdx.x * 256 + threadIdx.x;
    int d = tid & 255;
    int s = (tid >> 8) & (NSEG - 1);
    int b = tid >> 14;
    size_t base = ((size_t)b * TT + (size_t)s * SEGL) * DD + d;
    float c = g_carry[(b * NSEG + s) * DD + d];
    #pragma unroll 4
    for (int i = 0; i < SEGL; i++) {
        size_t idx = base + (size_t)i * DD;
        float f = g_f[idx];
        float z = g_z[idx];
        float o = g_o[idx];
        c = f * c + (1.0f - f) * z;
        out[idx] = o * c;
    }
}

// ---------------- launch ----------------
extern "C" void kernel_launch(void* const* d_in, const int* in_sizes, int n_in,
                              void* d_out, int out_size) {
    const float* x   = (const float*)d_in[0];
    const float* Wz  = (const float*)d_in[1];
    const float* Wf  = (const float*)d_in[2];
    const float* Wo  = (const float*)d_in[3];
    const float* bz  = (const float*)d_in[4];
    const float* bfv = (const float*)d_in[5];
    const float* bo  = (const float*)d_in[6];
    float* out = (float*)d_out;

    cudaFuncSetAttribute(gates_gemm, cudaFuncAttributeMaxDynamicSharedMemorySize, DYN_SMEM);

    cvt_x<<<(MTOT * DD / 4) / 256, 256>>>(x);
    trans_w<<<dim3(64, 2, 3), dim3(32, 8)>>>(Wz, Wf, Wo);
    gates_gemm<<<dim3(768 / BN, MTOT / BM), 256, DYN_SMEM>>>(bz, bfv, bo);
    seg_reduce<<<(BB * NSEG * DD) / 256, 256>>>();
    seg_carry<<<(BB * DD) / 256, 256>>>();
    seg_apply<<<(BB * NSEG * DD) / 256, 256>>>(out);
}